// round 3
// baseline (speedup 1.0000x reference)
#include <cuda_runtime.h>
#include <math.h>

// Problem constants
#define Bsz   4096
#define Nn    32
#define Hh    8
#define Dd    64
#define HIDd  512
#define MROWS (Bsz * Nn)                 // 131072
#define QKV_COLS (3 * HIDd)              // 1536

static const size_t OUT_ELEMS  = (size_t)MROWS * HIDd;        // 67108864
static const size_t ATTN_ELEMS = (size_t)Bsz * Hh * Nn * Nn;  // 33554432

// Scratch (no allocations allowed anywhere)
__device__ float g_qkv[(size_t)MROWS * QKV_COLS];   // ~805 MB
__device__ float g_ctx[(size_t)MROWS * HIDd];       // ~268 MB
__device__ float g_attn_fb[(size_t)Bsz * Hh * Nn * Nn];
__device__ unsigned int g_mask_bits[32];

// ---------------------------------------------------------------------------
// Mask decode: sparse_mask is bool [32,32]; storage width is ambiguous
// (1-byte bool vs 4-byte int32/float32). Diagonal is always true, so under
// 1-byte storage raw[33*i] != 0 for all i; under 4-byte 0/1 storage at least
// one of those bytes is 0. Build per-row bitmasks.
// ---------------------------------------------------------------------------
__global__ void decode_mask_kernel(const unsigned char* __restrict__ raw) {
    __shared__ int onebyte;
    if (threadIdx.x == 0) {
        int ok = 1;
        for (int i = 0; i < 32; ++i) if (raw[33 * i] == 0) ok = 0;
        onebyte = ok;
    }
    __syncthreads();
    int i = threadIdx.x;  // row
    unsigned int bits = 0;
    if (onebyte) {
        for (int j = 0; j < 32; ++j)
            if (raw[i * 32 + j] != 0) bits |= (1u << j);
    } else {
        const unsigned int* w = (const unsigned int*)raw;
        for (int j = 0; j < 32; ++j)
            if (w[i * 32 + j] != 0) bits |= (1u << j);
    }
    g_mask_bits[i] = bits;
}

// ---------------------------------------------------------------------------
// SGEMM (NT): C[m,n] = sum_k A[m,k]*B[n,k] + bias[n]
// A: [M,K] row-major, B: [N,K] row-major, C: [M,N] row-major.
// BM=BN=128, BK=16, 256 threads, 8x8 register tiles. M,N,K are multiples of
// the tile sizes here, so no bounds checks.
// ---------------------------------------------------------------------------
#define GBM 128
#define GBN 128
#define GBK 16
#define GTM 8
#define GTN 8

__global__ void __launch_bounds__(256)
sgemm_nt_bias(const float* __restrict__ A, const float* __restrict__ B,
              const float* __restrict__ bias, float* __restrict__ C,
              int M, int N, int K)
{
    __shared__ float As[GBK][GBM + 4];
    __shared__ float Bs[GBK][GBN + 4];

    const int bm = blockIdx.x * GBM;
    const int bn = blockIdx.y * GBN;
    const int t  = threadIdx.x;

    const int tx = t & 15;        // 0..15  (N direction)
    const int ty = t >> 4;        // 0..15  (M direction)
    const int row0 = ty * GTM;
    const int col0 = tx * GTN;

    float acc[GTM][GTN];
#pragma unroll
    for (int i = 0; i < GTM; ++i)
#pragma unroll
        for (int j = 0; j < GTN; ++j) acc[i][j] = 0.0f;

    for (int k0 = 0; k0 < K; k0 += GBK) {
        // Load 128x16 tiles of A and B (512 float4 each, 2 per thread),
        // stored transposed: [k][row].
#pragma unroll
        for (int r = 0; r < 2; ++r) {
            int idx = t + 256 * r;          // 0..511
            int row = idx >> 2;             // 0..127
            int kq  = (idx & 3) * 4;        // 0,4,8,12
            float4 a4 = *(const float4*)&A[(size_t)(bm + row) * K + k0 + kq];
            As[kq + 0][row] = a4.x;
            As[kq + 1][row] = a4.y;
            As[kq + 2][row] = a4.z;
            As[kq + 3][row] = a4.w;
            float4 b4 = *(const float4*)&B[(size_t)(bn + row) * K + k0 + kq];
            Bs[kq + 0][row] = b4.x;
            Bs[kq + 1][row] = b4.y;
            Bs[kq + 2][row] = b4.z;
            Bs[kq + 3][row] = b4.w;
        }
        __syncthreads();

#pragma unroll
        for (int kk = 0; kk < GBK; ++kk) {
            float a[GTM], b[GTN];
            *(float4*)&a[0] = *(const float4*)&As[kk][row0];
            *(float4*)&a[4] = *(const float4*)&As[kk][row0 + 4];
            *(float4*)&b[0] = *(const float4*)&Bs[kk][col0];
            *(float4*)&b[4] = *(const float4*)&Bs[kk][col0 + 4];
#pragma unroll
            for (int i = 0; i < GTM; ++i)
#pragma unroll
                for (int j = 0; j < GTN; ++j)
                    acc[i][j] += a[i] * b[j];
        }
        __syncthreads();
    }

    float bb[GTN];
#pragma unroll
    for (int j = 0; j < GTN; ++j) bb[j] = bias[bn + col0 + j];

#pragma unroll
    for (int i = 0; i < GTM; ++i) {
        size_t off = (size_t)(bm + row0 + i) * N + bn + col0;
        float4 o0, o1;
        o0.x = acc[i][0] + bb[0]; o0.y = acc[i][1] + bb[1];
        o0.z = acc[i][2] + bb[2]; o0.w = acc[i][3] + bb[3];
        o1.x = acc[i][4] + bb[4]; o1.y = acc[i][5] + bb[5];
        o1.z = acc[i][6] + bb[6]; o1.w = acc[i][7] + bb[7];
        *(float4*)&C[off]     = o0;
        *(float4*)&C[off + 4] = o1;
    }
}

// ---------------------------------------------------------------------------
// Attention: one block per (b,h). Q,K,V are 32x64 slices of g_qkv.
// scores = QK^T/8, mask (-1e9), softmax, attn out, ctx = P @ V.
// ---------------------------------------------------------------------------
__global__ void __launch_bounds__(128)
attn_kernel(const float* __restrict__ qkv, float* __restrict__ ctx,
            float* __restrict__ attn_out)
{
    __shared__ float Qs[32][64];
    __shared__ float Ks[32][65];   // pad -> conflict-free K[j][d] with j varying
    __shared__ float Vs[32][64];
    __shared__ float Ss[32][33];   // pad -> conflict-free row access

    const int bh = blockIdx.x;           // b*H + h
    const int b  = bh >> 3;
    const int h  = bh & 7;
    const int t  = threadIdx.x;

    const float* base = qkv + (size_t)b * Nn * QKV_COLS + h * Dd;

    // Load Q/K/V (512 float4 each matrix; 4 per thread per matrix)
#pragma unroll
    for (int r = 0; r < 4; ++r) {
        int idx = t + 128 * r;           // 0..511
        int i   = idx >> 4;              // row 0..31
        int d4  = (idx & 15) * 4;        // 0..60
        size_t ro = (size_t)i * QKV_COLS + d4;
        float4 q = *(const float4*)&base[ro];
        float4 k = *(const float4*)&base[ro + HIDd];
        float4 v = *(const float4*)&base[ro + 2 * HIDd];
        *(float4*)&Qs[i][d4] = q;
        Ks[i][d4 + 0] = k.x; Ks[i][d4 + 1] = k.y;
        Ks[i][d4 + 2] = k.z; Ks[i][d4 + 3] = k.w;
        *(float4*)&Vs[i][d4] = v;
    }
    __syncthreads();

    // Scores + mask. Lane-contiguous j => Qs broadcast, Ks conflict-free.
#pragma unroll
    for (int r = 0; r < 8; ++r) {
        int p = t + 128 * r;             // 0..1023
        int i = p >> 5, j = p & 31;
        float s = 0.0f;
#pragma unroll
        for (int d = 0; d < 64; ++d) s += Qs[i][d] * Ks[j][d];
        bool m = (g_mask_bits[i] >> j) & 1u;
        Ss[i][j] = m ? s * 0.125f : -1e9f;
    }
    __syncthreads();

    // Softmax: one thread per row (exact expf for fp32 parity)
    if (t < 32) {
        float mx = -1e30f;
#pragma unroll
        for (int j = 0; j < 32; ++j) mx = fmaxf(mx, Ss[t][j]);
        float sum = 0.0f;
#pragma unroll
        for (int j = 0; j < 32; ++j) {
            float e = expf(Ss[t][j] - mx);
            Ss[t][j] = e;
            sum += e;
        }
        float inv = 1.0f / sum;
#pragma unroll
        for (int j = 0; j < 32; ++j) Ss[t][j] *= inv;
    }
    __syncthreads();

    // Write attn [b,H,n,n]
    size_t abase = (size_t)bh * 1024;
#pragma unroll
    for (int r = 0; r < 8; ++r) {
        int p = t + 128 * r;
        attn_out[abase + p] = Ss[p >> 5][p & 31];
    }

    // ctx = P @ V, write to [b, n, h*64 + d]
    float* cbase = ctx + (size_t)b * Nn * HIDd + h * Dd;
#pragma unroll
    for (int r = 0; r < 16; ++r) {
        int o = t + 128 * r;             // 0..2047
        int i = o >> 6, d = o & 63;
        float acc = 0.0f;
#pragma unroll
        for (int j = 0; j < 32; ++j) acc += Ss[i][j] * Vs[j][d];
        cbase[(size_t)i * HIDd + d] = acc;
    }
}

// ---------------------------------------------------------------------------
// Launch
// ---------------------------------------------------------------------------
extern "C" void kernel_launch(void* const* d_in, const int* in_sizes, int n_in,
                              void* d_out, int out_size) {
    const float*         X    = (const float*)d_in[0];
    const unsigned char* mask = (const unsigned char*)d_in[1];
    const float*         Wqkv = (const float*)d_in[2];
    const float*         bqkv = (const float*)d_in[3];
    const float*         Wo   = (const float*)d_in[4];
    const float*         bo   = (const float*)d_in[5];

    float *qkv_p, *ctx_p, *attn_fb_p;
    cudaGetSymbolAddress((void**)&qkv_p, g_qkv);
    cudaGetSymbolAddress((void**)&ctx_p, g_ctx);
    cudaGetSymbolAddress((void**)&attn_fb_p, g_attn_fb);

    float* out = (float*)d_out;
    float* out_p;
    float* attn_p;
    long long osz = (long long)out_size;
    if (osz >= (long long)(OUT_ELEMS + ATTN_ELEMS)) {
        out_p  = out;
        attn_p = out + OUT_ELEMS;
    } else if (osz >= (long long)OUT_ELEMS) {
        out_p  = out;
        attn_p = attn_fb_p;
    } else {
        // d_out only fits attn (defensive)
        attn_p = out;
        out_p  = qkv_p;  // qkv scratch is dead after attention
    }

    decode_mask_kernel<<<1, 32>>>(mask);

    // qkv = X @ Wqkv^T + bqkv   [131072 x 1536]
    sgemm_nt_bias<<<dim3(MROWS / GBM, QKV_COLS / GBN), 256>>>(
        X, Wqkv, bqkv, qkv_p, MROWS, QKV_COLS, HIDd);

    // attention per (b,h)
    attn_kernel<<<Bsz * Hh, 128>>>(qkv_p, ctx_p, attn_p);

    // out = ctx @ Wo^T + bo     [131072 x 512]
    sgemm_nt_bias<<<dim3(MROWS / GBM, HIDd / GBN), 256>>>(
        ctx_p, Wo, bo, out_p, MROWS, HIDd, HIDd);
}